// round 7
// baseline (speedup 1.0000x reference)
#include <cuda_runtime.h>
#include <cuda_bf16.h>
#include <math.h>
#include <stdint.h>

#define SEQ    512
#define BATCH  64
#define DIM    512
#define HID    1024
#define GATES  4096
#define NCTA   128
#define NTHR   256

// ---------------------------------------------------------------------------
// Device scratch (allocation-free rule)
// ---------------------------------------------------------------------------
__device__ float          g_gx[(size_t)SEQ * BATCH * GATES];   // input projection (fp32)
__device__ __nv_bfloat16  g_xh[(size_t)SEQ * BATCH * DIM];     // x split hi  [m][k]
__device__ __nv_bfloat16  g_xl[(size_t)SEQ * BATCH * DIM];     // x split lo
__device__ __nv_bfloat16  g_wxt_hi[(size_t)GATES * DIM];       // WxT split hi [n][k]
__device__ __nv_bfloat16  g_wxt_lo[(size_t)GATES * DIM];       // WxT split lo
__device__ __nv_bfloat16  g_wt_hi[(size_t)GATES * HID];        // WhT split hi [n][k]
__device__ __nv_bfloat16  g_wt_lo[(size_t)GATES * HID];        // WhT split lo
__device__ __nv_bfloat16  g_h_hi[2][BATCH * HID];              // ping-pong hidden, hi
__device__ __nv_bfloat16  g_h_lo[2][BATCH * HID];              // ping-pong hidden, lo
__device__ unsigned       g_hflag[NCTA];                       // per-CTA h completion (step+1)
__device__ unsigned       g_bar_cnt;
__device__ unsigned       g_bar_gen;

// ---------------------------------------------------------------------------
// PTX helpers
// ---------------------------------------------------------------------------
__device__ __forceinline__ uint32_t smem_u32(const void* p) {
    uint32_t a;
    asm("{ .reg .u64 t; cvta.to.shared.u64 t, %1; cvt.u32.u64 %0, t; }" : "=r"(a) : "l"(p));
    return a;
}

#define LDSM_X4(r0, r1, r2, r3, addr) \
    asm volatile("ldmatrix.sync.aligned.m8n8.x4.shared.b16 {%0,%1,%2,%3}, [%4];" \
                 : "=r"(r0), "=r"(r1), "=r"(r2), "=r"(r3) : "r"(addr))

#define MMA16816(c, a0, a1, a2, a3, b0, b1) \
    asm volatile("mma.sync.aligned.m16n8k16.row.col.f32.bf16.bf16.f32 " \
                 "{%0,%1,%2,%3}, {%4,%5,%6,%7}, {%8,%9}, {%0,%1,%2,%3};" \
                 : "+f"((c)[0]), "+f"((c)[1]), "+f"((c)[2]), "+f"((c)[3]) \
                 : "r"(a0), "r"(a1), "r"(a2), "r"(a3), "r"(b0), "r"(b1))

__device__ __forceinline__ void cpa16(uint32_t dst, const void* src) {
    asm volatile("cp.async.cg.shared.global [%0], [%1], 16;" :: "r"(dst), "l"(src));
}
#define CPA_COMMIT() asm volatile("cp.async.commit_group;" ::: "memory")
#define CPA_WAIT(n)  asm volatile("cp.async.wait_group %0;" :: "n"(n) : "memory")

__device__ __forceinline__ unsigned ld_acq(const unsigned* p) {
    unsigned v;
    asm volatile("ld.acquire.gpu.u32 %0, [%1];" : "=r"(v) : "l"(p) : "memory");
    return v;
}
__device__ __forceinline__ void st_rel(unsigned* p, unsigned v) {
    asm volatile("st.release.gpu.u32 [%0], %1;" :: "l"(p), "r"(v) : "memory");
}

// ---------------------------------------------------------------------------
// Split kernels
// ---------------------------------------------------------------------------
__global__ void split_x(const float* __restrict__ x) {
    size_t i = (size_t)blockIdx.x * blockDim.x + threadIdx.x;
    if (i < (size_t)SEQ * BATCH * DIM) {
        float v = x[i];
        __nv_bfloat16 hh = __float2bfloat16(v);
        g_xh[i] = hh;
        g_xl[i] = __float2bfloat16(v - __bfloat162float(hh));
    }
}

__global__ void split_wxt(const float* __restrict__ Wx) {
    int n = blockIdx.x;
    int k = threadIdx.x;
    float w = Wx[(size_t)k * GATES + n];
    __nv_bfloat16 hh = __float2bfloat16(w);
    g_wxt_hi[(size_t)n * DIM + k] = hh;
    g_wxt_lo[(size_t)n * DIM + k] = __float2bfloat16(w - __bfloat162float(hh));
}

__global__ void split_wh(const float* __restrict__ Wh) {
    int n = blockIdx.x;
    for (int k = threadIdx.x; k < HID; k += blockDim.x) {
        float w = Wh[(size_t)k * GATES + n];
        __nv_bfloat16 hh = __float2bfloat16(w);
        g_wt_hi[(size_t)n * HID + k] = hh;
        g_wt_lo[(size_t)n * HID + k] = __float2bfloat16(w - __bfloat162float(hh));
    }
}

__global__ void split_h0(const float* __restrict__ h0) {
    int i = blockIdx.x * blockDim.x + threadIdx.x;
    if (i < BATCH * HID) {
        float v = h0[i];
        __nv_bfloat16 hh = __float2bfloat16(v);
        g_h_hi[0][i] = hh;
        g_h_lo[0][i] = __float2bfloat16(v - __bfloat162float(hh));
    }
}

// ---------------------------------------------------------------------------
// gx = x @ Wx via bf16 hi/lo 3-pass mma.sync.
// Block tile 128x128, 8 warps (2m x 4n), warp 64x32. K-chunk 64, double-buffered.
// SMEM rows: 64 k bf16 = 128 B + 16 pad = 144 B stride.
// ---------------------------------------------------------------------------
#define GA_STR   144u
#define GS_AHI   0u
#define GS_ALO   18432u
#define GS_BHI   36864u
#define GS_BLO   55296u
#define GS_STAGE 73728u
#define GS_TOTAL 147456u

__global__ void __launch_bounds__(256, 1)
gx_mma(float* __restrict__ dummy) {
    extern __shared__ char sm[];
    const uint32_t sb = smem_u32(sm);

    const int tid = threadIdx.x;
    const int wid = tid >> 5;
    const int lid = tid & 31;
    const int wm = wid >> 2;
    const int wn = wid & 3;
    const int bm = blockIdx.y * 128;
    const int bn = blockIdx.x * 128;

    const uint32_t a_lane = (uint32_t)(wm * 64 + (lid & 15)) * GA_STR + (uint32_t)(lid >> 4) * 16u;
    const uint32_t b_lane = (uint32_t)(wn * 32 + (lid & 7) + ((lid >> 4) << 3)) * GA_STR
                          + (uint32_t)((lid >> 3) & 1) * 16u;

    // prologue: chunk 0 (k=0..63)
    {
        #pragma unroll
        for (int i = 0; i < 4; i++) {
            int e = tid + i * 256;              // 0..1023
            int r = e >> 3, u = e & 7;
            uint32_t du = (uint32_t)r * GA_STR + (uint32_t)u * 16u;
            cpa16(sb + GS_AHI + du, g_xh + (size_t)(bm + r) * DIM + u * 8);
            cpa16(sb + GS_ALO + du, g_xl + (size_t)(bm + r) * DIM + u * 8);
            cpa16(sb + GS_BHI + du, g_wxt_hi + (size_t)(bn + r) * DIM + u * 8);
            cpa16(sb + GS_BLO + du, g_wxt_lo + (size_t)(bn + r) * DIM + u * 8);
        }
        CPA_COMMIT();
    }

    float acc[64] = {};

    #pragma unroll 1
    for (int c = 0; c < 8; c++) {
        if (c < 7) {
            uint32_t stg = (uint32_t)((c + 1) & 1) * GS_STAGE;
            int kc = (c + 1) * 64;
            #pragma unroll
            for (int i = 0; i < 4; i++) {
                int e = tid + i * 256;
                int r = e >> 3, u = e & 7;
                uint32_t du = stg + (uint32_t)r * GA_STR + (uint32_t)u * 16u;
                cpa16(sb + GS_AHI + du, g_xh + (size_t)(bm + r) * DIM + kc + u * 8);
                cpa16(sb + GS_ALO + du, g_xl + (size_t)(bm + r) * DIM + kc + u * 8);
                cpa16(sb + GS_BHI + du, g_wxt_hi + (size_t)(bn + r) * DIM + kc + u * 8);
                cpa16(sb + GS_BLO + du, g_wxt_lo + (size_t)(bn + r) * DIM + kc + u * 8);
            }
            CPA_COMMIT();
            CPA_WAIT(1);
        } else {
            CPA_WAIT(0);
        }
        __syncthreads();

        const uint32_t stg = (uint32_t)(c & 1) * GS_STAGE;
        const uint32_t abase = sb + stg + a_lane;
        const uint32_t bbase = sb + stg + b_lane;

        #pragma unroll
        for (int kk = 0; kk < 4; kk++) {
            uint32_t bhf[8], blf[8];
            #pragma unroll
            for (int bt = 0; bt < 2; bt++) {
                LDSM_X4(bhf[bt * 4], bhf[bt * 4 + 1], bhf[bt * 4 + 2], bhf[bt * 4 + 3],
                        bbase + GS_BHI + (uint32_t)bt * (16u * GA_STR) + kk * 32u);
                LDSM_X4(blf[bt * 4], blf[bt * 4 + 1], blf[bt * 4 + 2], blf[bt * 4 + 3],
                        bbase + GS_BLO + (uint32_t)bt * (16u * GA_STR) + kk * 32u);
            }
            #pragma unroll
            for (int mt = 0; mt < 4; mt++) {
                uint32_t ah0, ah1, ah2, ah3, al0, al1, al2, al3;
                uint32_t ao = (uint32_t)mt * (16u * GA_STR) + kk * 32u;
                LDSM_X4(ah0, ah1, ah2, ah3, abase + GS_AHI + ao);
                LDSM_X4(al0, al1, al2, al3, abase + GS_ALO + ao);
                #pragma unroll
                for (int j = 0; j < 4; j++) {
                    float* a = acc + (mt * 4 + j) * 4;
                    uint32_t b0 = (j & 1) ? bhf[(j >> 1) * 4 + 2] : bhf[(j >> 1) * 4 + 0];
                    uint32_t b1 = (j & 1) ? bhf[(j >> 1) * 4 + 3] : bhf[(j >> 1) * 4 + 1];
                    uint32_t c0 = (j & 1) ? blf[(j >> 1) * 4 + 2] : blf[(j >> 1) * 4 + 0];
                    uint32_t c1 = (j & 1) ? blf[(j >> 1) * 4 + 3] : blf[(j >> 1) * 4 + 1];
                    MMA16816(a, ah0, ah1, ah2, ah3, b0, b1);
                    MMA16816(a, ah0, ah1, ah2, ah3, c0, c1);
                    MMA16816(a, al0, al1, al2, al3, b0, b1);
                }
            }
        }
        __syncthreads();
    }

    #pragma unroll
    for (int mt = 0; mt < 4; mt++) {
        int r0 = bm + wm * 64 + mt * 16 + (lid >> 2);
        #pragma unroll
        for (int j = 0; j < 4; j++) {
            const float* a = acc + (mt * 4 + j) * 4;
            int col = bn + wn * 32 + j * 8 + (lid & 3) * 2;
            *reinterpret_cast<float2*>(&g_gx[(size_t)r0 * GATES + col]) = make_float2(a[0], a[1]);
            *reinterpret_cast<float2*>(&g_gx[(size_t)(r0 + 8) * GATES + col]) = make_float2(a[2], a[3]);
        }
    }
}

// ---------------------------------------------------------------------------
// SMEM layout for recurrence (unchanged, validated)
// ---------------------------------------------------------------------------
#define BSTR     2064u
#define ASTR     272u
#define SM_BHI   0u
#define SM_BLO   66048u
#define SM_A     132096u
#define A_STAGE  34816u
#define A_LO     17408u
#define SM_GX    201728u
#define GXSTR    144u
#define SM_SG    210944u
#define SM_BIAS  219648u
#define SM_TOTAL 219776u

// ---------------------------------------------------------------------------
// Persistent LSTM recurrence. Flag-based inter-CTA sync (no central barrier).
// ---------------------------------------------------------------------------
__global__ void __launch_bounds__(NTHR, 1)
lstm_persist(const float* __restrict__ c0, const float* __restrict__ bh,
             float* __restrict__ out) {
    extern __shared__ char sm[];
    const uint32_t sb = smem_u32(sm);

    const int tid = threadIdx.x;
    const int wid = tid >> 5;
    const int lid = tid & 31;
    const int hb  = blockIdx.x;

    // reset my flag (replay safety), then one generation barrier
    if (tid == 0) *((volatile unsigned*)&g_hflag[hb]) = 0u;

    for (int idx = tid; idx < 32 * 128; idx += NTHR) {
        int n = idx >> 7, u = idx & 127;
        int gr = (n >> 3) * HID + hb * 8 + (n & 7);
        uint32_t dst = n * BSTR + u * 16u;
        *reinterpret_cast<uint4*>(sm + SM_BHI + dst) =
            *reinterpret_cast<const uint4*>(g_wt_hi + (size_t)gr * HID + u * 8);
        *reinterpret_cast<uint4*>(sm + SM_BLO + dst) =
            *reinterpret_cast<const uint4*>(g_wt_lo + (size_t)gr * HID + u * 8);
    }

    if (tid < 32) {
        int gc = (tid >> 3) * HID + hb * 8 + (tid & 7);
        *reinterpret_cast<float*>(sm + SM_BIAS + tid * 4) = bh[gc];
    }

    // cell state: 2 items per thread, item e = tid + q*256 -> (b = e>>3, j = e&7)
    float c2[2];
    #pragma unroll
    for (int q = 0; q < 2; q++) {
        int e = tid + q * NTHR;
        c2[q] = c0[(e >> 3) * HID + hb * 8 + (e & 7)];
    }
    __syncthreads();

    // one grid barrier: ensures all CTAs reset flags before anyone sets them
    if (tid == 0) {
        __threadfence();
        unsigned gen = *((volatile unsigned*)&g_bar_gen);
        unsigned arr = atomicAdd(&g_bar_cnt, 1);
        if (arr == NCTA - 1) {
            atomicExch(&g_bar_cnt, 0);
            __threadfence();
            atomicAdd(&g_bar_gen, 1);
        } else {
            while (*((volatile unsigned*)&g_bar_gen) == gen) __nanosleep(40);
        }
    }
    __syncthreads();

    const int mt = wid & 3;
    const int nh = wid >> 2;
    const uint32_t a_lane = (uint32_t)(mt * 16 + (lid & 15)) * ASTR + (uint32_t)(lid >> 4) * 16u;
    const uint32_t b_lane = (uint32_t)(nh * 16 + (lid & 7) + ((lid >> 4) << 3)) * BSTR
                          + (uint32_t)((lid >> 3) & 1) * 16u;
    const float* bsm = reinterpret_cast<const float*>(sm + SM_BIAS);

    for (int t = 0; t < SEQ; t++) {
        // wait for all CTAs to have published h for step t (t=0: from split_h0)
        if (t > 0) {
            if (tid < NCTA) {
                while (ld_acq(&g_hflag[tid]) < (unsigned)t) { }
            }
            __syncthreads();
        }

        const __nv_bfloat16* hs_hi = g_h_hi[t & 1];
        const __nv_bfloat16* hs_lo = g_h_lo[t & 1];

        {
            #pragma unroll
            for (int i = 0; i < 4; i++) {
                int e = tid + i * NTHR;
                int r = e >> 4, u = e & 15;
                uint32_t dst = SM_A + (uint32_t)r * ASTR + (uint32_t)u * 16u;
                cpa16(sb + dst,        hs_hi + r * HID + u * 8);
                cpa16(sb + dst + A_LO, hs_lo + r * HID + u * 8);
            }
            #pragma unroll
            for (int i = 0; i < 2; i++) {
                int e = tid + i * NTHR;
                int r = e >> 3, u = e & 7;
                const float* src = g_gx + ((size_t)t * BATCH + r) * GATES
                                 + (u >> 1) * HID + hb * 8 + (u & 1) * 4;
                cpa16(sb + SM_GX + (uint32_t)r * GXSTR + (uint32_t)u * 16u, src);
            }
            CPA_COMMIT();
        }

        float acc[8] = {};

        #pragma unroll 1
        for (int c = 0; c < 8; c++) {
            if (c < 7) {
                uint32_t stg = SM_A + (uint32_t)((c + 1) & 1) * A_STAGE;
                int kc = (c + 1) * 128;
                #pragma unroll
                for (int i = 0; i < 4; i++) {
                    int e = tid + i * NTHR;
                    int r = e >> 4, u = e & 15;
                    uint32_t dst = stg + (uint32_t)r * ASTR + (uint32_t)u * 16u;
                    cpa16(sb + dst,        hs_hi + r * HID + kc + u * 8);
                    cpa16(sb + dst + A_LO, hs_lo + r * HID + kc + u * 8);
                }
                CPA_COMMIT();
                CPA_WAIT(1);
            } else {
                CPA_WAIT(0);
            }
            __syncthreads();

            const uint32_t a_hi = sb + SM_A + (uint32_t)(c & 1) * A_STAGE + a_lane;
            const uint32_t a_lo = a_hi + A_LO;
            const uint32_t b_hi = sb + SM_BHI + b_lane + (uint32_t)c * 256u;
            const uint32_t b_lo = b_hi + (SM_BLO - SM_BHI);

            #pragma unroll
            for (int kk = 0; kk < 8; kk++) {
                uint32_t ah0, ah1, ah2, ah3, al0, al1, al2, al3;
                uint32_t bh0, bh1, bh2, bh3, bl0, bl1, bl2, bl3;
                LDSM_X4(ah0, ah1, ah2, ah3, a_hi + kk * 32u);
                LDSM_X4(bh0, bh1, bh2, bh3, b_hi + kk * 32u);
                LDSM_X4(al0, al1, al2, al3, a_lo + kk * 32u);
                LDSM_X4(bl0, bl1, bl2, bl3, b_lo + kk * 32u);

                MMA16816(acc,     ah0, ah1, ah2, ah3, bh0, bh1);
                MMA16816(acc + 4, ah0, ah1, ah2, ah3, bh2, bh3);
                MMA16816(acc,     ah0, ah1, ah2, ah3, bl0, bl1);
                MMA16816(acc + 4, ah0, ah1, ah2, ah3, bl2, bl3);
                MMA16816(acc,     al0, al1, al2, al3, bh0, bh1);
                MMA16816(acc + 4, al0, al1, al2, al3, bh2, bh3);
            }
            __syncthreads();
        }

        // stage gates
        {
            float* sg = reinterpret_cast<float*>(sm + SM_SG);
            int r0 = mt * 16 + (lid >> 2);
            int cb = nh * 16 + (lid & 3) * 2;
            #pragma unroll
            for (int ng = 0; ng < 2; ng++) {
                float* p0 = sg + (size_t)r0 * 34 + cb + ng * 8;
                float* p1 = sg + (size_t)(r0 + 8) * 34 + cb + ng * 8;
                p0[0] = acc[ng * 4 + 0]; p0[1] = acc[ng * 4 + 1];
                p1[0] = acc[ng * 4 + 2]; p1[1] = acc[ng * 4 + 3];
            }
        }
        __syncthreads();

        // elementwise across all 256 threads (2 items each)
        {
            const float* sg = reinterpret_cast<const float*>(sm + SM_SG);
            __nv_bfloat16* hd_hi = g_h_hi[(t + 1) & 1];
            __nv_bfloat16* hd_lo = g_h_lo[(t + 1) & 1];

            #pragma unroll
            for (int q = 0; q < 2; q++) {
                int e = tid + q * NTHR;
                int b = e >> 3, j = e & 7;
                const float* row_sg = sg + (size_t)b * 34;
                const float* gxrow = reinterpret_cast<const float*>(sm + SM_GX + (uint32_t)b * GXSTR);

                float gi = row_sg[j]      + gxrow[j]      + bsm[j];
                float gf = row_sg[8 + j]  + gxrow[8 + j]  + bsm[8 + j];
                float gj = row_sg[16 + j] + gxrow[16 + j] + bsm[16 + j];
                float go = row_sg[24 + j] + gxrow[24 + j] + bsm[24 + j];

                float si = 1.0f / (1.0f + expf(-gi));
                float sf = 1.0f / (1.0f + expf(-(gf + 1.0f)));   // FORGET_BIAS
                float so = 1.0f / (1.0f + expf(-go));
                float cn = c2[q] * sf + si * tanhf(gj);
                c2[q] = cn;
                float hv = tanhf(cn) * so;

                int gidx = b * HID + hb * 8 + j;
                if (t < SEQ - 1) {
                    __nv_bfloat16 hh = __float2bfloat16(hv);
                    hd_hi[gidx] = hh;
                    hd_lo[gidx] = __float2bfloat16(hv - __bfloat162float(hh));
                } else {
                    out[gidx] = hv;
                    out[BATCH * HID + gidx] = cn;
                }
            }
        }
        __syncthreads();

        // publish my h slice for step t+1
        if (t < SEQ - 1 && tid == 0) {
            __threadfence();
            st_rel(&g_hflag[hb], (unsigned)(t + 1));
        }
    }
}

// ---------------------------------------------------------------------------
extern "C" void kernel_launch(void* const* d_in, const int* in_sizes, int n_in,
                              void* d_out, int out_size) {
    const float* x  = (const float*)d_in[0];
    const float* h0 = (const float*)d_in[1];
    const float* c0 = (const float*)d_in[2];
    const float* Wx = (const float*)d_in[3];
    const float* Wh = (const float*)d_in[4];
    const float* bh = (const float*)d_in[5];
    float* out = (float*)d_out;

    cudaFuncSetAttribute(gx_mma, cudaFuncAttributeMaxDynamicSharedMemorySize, GS_TOTAL);
    cudaFuncSetAttribute(lstm_persist, cudaFuncAttributeMaxDynamicSharedMemorySize, SM_TOTAL);

    split_x<<<(SEQ * BATCH * DIM + 255) / 256, 256>>>(x);
    split_wxt<<<GATES, DIM>>>(Wx);
    split_wh<<<GATES, 256>>>(Wh);
    split_h0<<<64, 1024>>>(h0);
    gx_mma<<<dim3(GATES / 128, (SEQ * BATCH) / 128), 256, GS_TOTAL>>>(nullptr);
    lstm_persist<<<NCTA, NTHR, SM_TOTAL>>>(c0, bh, out);
}